// round 1
// baseline (speedup 1.0000x reference)
#include <cuda_runtime.h>
#include <math.h>

#define NN 50000
#define EE 800000
#define ET (EE + NN)
#define FIN 256
#define HH 64
#define CC 40
#define NEG_SLOPE 0.2f

// ---------------- scratch (__device__ globals; no allocation) ----------------
static __device__ int g_is64;
static __device__ int g_src[ET];
static __device__ int g_dst[ET];

static __device__ float g_xl1[NN * HH];
static __device__ float g_xr1[NN * HH];
static __device__ float g_ln1[NN * HH];
static __device__ float g_agg1[NN * HH];
static __device__ float g_h[NN * HH];
static __device__ float g_e1[ET];
static __device__ unsigned g_emax1[NN];
static __device__ float g_den1[NN];

static __device__ float g_xl2[NN * CC];
static __device__ float g_xr2[NN * CC];
static __device__ float g_ln2[NN * CC];
static __device__ float g_agg2[NN * CC];
static __device__ float g_e2[ET];
static __device__ unsigned g_emax2[NN];
static __device__ float g_den2[NN];

// monotone float <-> unsigned encoding for atomicMax on floats (any sign)
__device__ __forceinline__ unsigned fenc(float f) {
    unsigned u = __float_as_uint(f);
    return (u & 0x80000000u) ? ~u : (u | 0x80000000u);
}
__device__ __forceinline__ float fdec(unsigned u) {
    return __uint_as_float((u & 0x80000000u) ? (u ^ 0x80000000u) : ~u);
}

// ---------------- edge index dtype detect + convert ----------------
// If the buffer is int64 (values < 2^31, nonnegative), every odd int32 word is 0.
__global__ void detect_kernel(const void* edge) {
    const int* p = (const int*)edge;
    int ok64 = 1;
    for (int i = threadIdx.x * 2 + 1; i < 4096; i += 64)
        if (p[i] != 0) ok64 = 0;
    unsigned b = __ballot_sync(0xffffffffu, ok64);
    if (threadIdx.x == 0) g_is64 = (b == 0xffffffffu) ? 1 : 0;
}

__global__ void convert_edges_kernel(const void* edge) {
    int t = blockIdx.x * blockDim.x + threadIdx.x;
    if (t >= ET) return;
    if (t >= EE) {  // appended self loops
        g_src[t] = t - EE;
        g_dst[t] = t - EE;
        return;
    }
    if (g_is64) {
        const long long* p = (const long long*)edge;
        g_src[t] = (int)p[t];
        g_dst[t] = (int)p[EE + t];
    } else {
        const int* p = (const int*)edge;
        g_src[t] = p[t];
        g_dst[t] = p[EE + t];
    }
}

// ---------------- per-launch scratch re-init (graph-replay safe) ----------------
__global__ void zero_kernel() {
    int i = blockIdx.x * blockDim.x + threadIdx.x;
    int gs = gridDim.x * blockDim.x;
    for (int j = i; j < NN * HH; j += gs) g_agg1[j] = 0.f;
    for (int j = i; j < NN * CC; j += gs) g_agg2[j] = 0.f;
    for (int j = i; j < NN; j += gs) {
        g_den1[j] = 0.f;
        g_den2[j] = 0.f;
        g_emax1[j] = 0u;   // fenc domain: 0 < any real encoding
        g_emax2[j] = 0u;
    }
}

// ---------------- layer1 node GEMMs: xl1/xr1/lin1 fused ----------------
// block = 64 threads (one per output col), 16 node rows per block, x tile in SMEM
__global__ void __launch_bounds__(64) gemm1_kernel(
    const float* __restrict__ x,
    const float* __restrict__ Wl, const float* __restrict__ bl,
    const float* __restrict__ Wr, const float* __restrict__ br,
    const float* __restrict__ Wn, const float* __restrict__ bn) {
    __shared__ float xs[16 * FIN];
    const int t = threadIdx.x;
    const int row0 = blockIdx.x * 16;
#pragma unroll
    for (int i = 0; i < 64; i++) xs[i * 64 + t] = x[row0 * FIN + i * 64 + t];
    __syncthreads();

    float al[16], ar[16], an[16];
#pragma unroll
    for (int m = 0; m < 16; m++) { al[m] = 0.f; ar[m] = 0.f; an[m] = 0.f; }

    for (int k = 0; k < FIN; k++) {
        float wl = __ldg(&Wl[k * HH + t]);
        float wr = __ldg(&Wr[k * HH + t]);
        float wn = __ldg(&Wn[k * HH + t]);
#pragma unroll
        for (int m = 0; m < 16; m++) {
            float xv = xs[m * FIN + k];
            al[m] = fmaf(xv, wl, al[m]);
            ar[m] = fmaf(xv, wr, ar[m]);
            an[m] = fmaf(xv, wn, an[m]);
        }
    }
    float vbl = __ldg(&bl[t]), vbr = __ldg(&br[t]), vbn = __ldg(&bn[t]);
#pragma unroll
    for (int m = 0; m < 16; m++) {
        int o = (row0 + m) * HH + t;
        g_xl1[o] = al[m] + vbl;
        g_xr1[o] = ar[m] + vbr;
        g_ln1[o] = an[m] + vbn;
    }
}

// ---------------- layer1 edge kernels ----------------
__global__ void edge_logits1_kernel(const float* __restrict__ att) {
    int w = (blockIdx.x * blockDim.x + threadIdx.x) >> 5;
    int lane = threadIdx.x & 31;
    if (w >= ET) return;
    int s = g_src[w], d = g_dst[w];
    float m1 = g_xl1[s * HH + lane] + g_xr1[d * HH + lane];
    float m2 = g_xl1[s * HH + 32 + lane] + g_xr1[d * HH + 32 + lane];
    m1 = (m1 > 0.f) ? m1 : NEG_SLOPE * m1;
    m2 = (m2 > 0.f) ? m2 : NEG_SLOPE * m2;
    float v = m1 * __ldg(&att[lane]) + m2 * __ldg(&att[lane + 32]);
#pragma unroll
    for (int o = 16; o > 0; o >>= 1) v += __shfl_xor_sync(0xffffffffu, v, o);
    if (lane == 0) {
        g_e1[w] = v;
        atomicMax(&g_emax1[d], fenc(v));
    }
}

__global__ void edge_exp1_kernel() {
    int t = blockIdx.x * blockDim.x + threadIdx.x;
    if (t >= ET) return;
    int d = g_dst[t];
    float ee = expf(g_e1[t] - fdec(g_emax1[d]));
    g_e1[t] = ee;
    atomicAdd(&g_den1[d], ee);
}

__global__ void edge_agg1_kernel() {
    int w = (blockIdx.x * blockDim.x + threadIdx.x) >> 5;
    int lane = threadIdx.x & 31;
    if (w >= ET) return;
    int s = g_src[w], d = g_dst[w];
    float alpha = g_e1[w] / g_den1[d];
    atomicAdd(&g_agg1[d * HH + lane], alpha * g_xl1[s * HH + lane]);
    atomicAdd(&g_agg1[d * HH + 32 + lane], alpha * g_xl1[s * HH + 32 + lane]);
}

__global__ void node1_kernel(const float* __restrict__ bias1) {
    int i = blockIdx.x * blockDim.x + threadIdx.x;
    if (i >= NN * HH) return;
    int c = i & (HH - 1);
    float v = g_agg1[i] + __ldg(&bias1[c]) + g_ln1[i];
    g_h[i] = fmaxf(v, 0.f);
}

// ---------------- layer2 node GEMMs (h @ W2l/W2r/lin2) ----------------
__global__ void __launch_bounds__(64) gemm2_kernel(
    const float* __restrict__ Wl, const float* __restrict__ bl,
    const float* __restrict__ Wr, const float* __restrict__ br,
    const float* __restrict__ Wn, const float* __restrict__ bn) {
    __shared__ float hs[16 * HH];
    const int t = threadIdx.x;
    const int row0 = blockIdx.x * 16;
#pragma unroll
    for (int i = 0; i < 16; i++) hs[i * 64 + t] = g_h[row0 * HH + i * 64 + t];
    __syncthreads();

    const bool act = (t < CC);
    float al[16], ar[16], an[16];
#pragma unroll
    for (int m = 0; m < 16; m++) { al[m] = 0.f; ar[m] = 0.f; an[m] = 0.f; }

    for (int k = 0; k < HH; k++) {
        float wl = act ? __ldg(&Wl[k * CC + t]) : 0.f;
        float wr = act ? __ldg(&Wr[k * CC + t]) : 0.f;
        float wn = act ? __ldg(&Wn[k * CC + t]) : 0.f;
#pragma unroll
        for (int m = 0; m < 16; m++) {
            float xv = hs[m * HH + k];
            al[m] = fmaf(xv, wl, al[m]);
            ar[m] = fmaf(xv, wr, ar[m]);
            an[m] = fmaf(xv, wn, an[m]);
        }
    }
    if (act) {
        float vbl = __ldg(&bl[t]), vbr = __ldg(&br[t]), vbn = __ldg(&bn[t]);
#pragma unroll
        for (int m = 0; m < 16; m++) {
            int o = (row0 + m) * CC + t;
            g_xl2[o] = al[m] + vbl;
            g_xr2[o] = ar[m] + vbr;
            g_ln2[o] = an[m] + vbn;
        }
    }
}

// ---------------- layer2 edge kernels (C = 40 dims) ----------------
__global__ void edge_logits2_kernel(const float* __restrict__ att) {
    int w = (blockIdx.x * blockDim.x + threadIdx.x) >> 5;
    int lane = threadIdx.x & 31;
    if (w >= ET) return;
    int s = g_src[w], d = g_dst[w];
    float m1 = g_xl2[s * CC + lane] + g_xr2[d * CC + lane];
    m1 = (m1 > 0.f) ? m1 : NEG_SLOPE * m1;
    float v = m1 * __ldg(&att[lane]);
    if (lane < CC - 32) {
        float m2 = g_xl2[s * CC + 32 + lane] + g_xr2[d * CC + 32 + lane];
        m2 = (m2 > 0.f) ? m2 : NEG_SLOPE * m2;
        v += m2 * __ldg(&att[32 + lane]);
    }
#pragma unroll
    for (int o = 16; o > 0; o >>= 1) v += __shfl_xor_sync(0xffffffffu, v, o);
    if (lane == 0) {
        g_e2[w] = v;
        atomicMax(&g_emax2[d], fenc(v));
    }
}

__global__ void edge_exp2_kernel() {
    int t = blockIdx.x * blockDim.x + threadIdx.x;
    if (t >= ET) return;
    int d = g_dst[t];
    float ee = expf(g_e2[t] - fdec(g_emax2[d]));
    g_e2[t] = ee;
    atomicAdd(&g_den2[d], ee);
}

__global__ void edge_agg2_kernel() {
    int w = (blockIdx.x * blockDim.x + threadIdx.x) >> 5;
    int lane = threadIdx.x & 31;
    if (w >= ET) return;
    int s = g_src[w], d = g_dst[w];
    float alpha = g_e2[w] / g_den2[d];
    atomicAdd(&g_agg2[d * CC + lane], alpha * g_xl2[s * CC + lane]);
    if (lane < CC - 32)
        atomicAdd(&g_agg2[d * CC + 32 + lane], alpha * g_xl2[s * CC + 32 + lane]);
}

// ---------------- final: o = agg2 + bias2 + lin2, then log_softmax ----------------
__global__ void node2_kernel(const float* __restrict__ bias2, float* __restrict__ out) {
    int w = (blockIdx.x * blockDim.x + threadIdx.x) >> 5;  // one warp per node
    int lane = threadIdx.x & 31;
    if (w >= NN) return;
    float v1 = g_agg2[w * CC + lane] + __ldg(&bias2[lane]) + g_ln2[w * CC + lane];
    float v2 = -INFINITY;
    if (lane < CC - 32)
        v2 = g_agg2[w * CC + 32 + lane] + __ldg(&bias2[32 + lane]) + g_ln2[w * CC + 32 + lane];

    float mx = fmaxf(v1, v2);
#pragma unroll
    for (int o = 16; o > 0; o >>= 1) mx = fmaxf(mx, __shfl_xor_sync(0xffffffffu, mx, o));

    float se = expf(v1 - mx) + ((lane < CC - 32) ? expf(v2 - mx) : 0.f);
#pragma unroll
    for (int o = 16; o > 0; o >>= 1) se += __shfl_xor_sync(0xffffffffu, se, o);
    float ls = logf(se);

    out[w * CC + lane] = v1 - mx - ls;
    if (lane < CC - 32) out[w * CC + 32 + lane] = v2 - mx - ls;
}

// edge_index passthrough (reference returns it as 2nd output), as float
__global__ void passthrough_kernel(float* __restrict__ out) {
    int t = blockIdx.x * blockDim.x + threadIdx.x;
    if (t >= EE) return;
    out[NN * CC + t] = (float)g_src[t];
    out[NN * CC + EE + t] = (float)g_dst[t];
}

// ---------------- launch ----------------
extern "C" void kernel_launch(void* const* d_in, const int* in_sizes, int n_in,
                              void* d_out, int out_size) {
    const float* x     = (const float*)d_in[0];
    const void*  ei    = d_in[1];
    const float* W1l   = (const float*)d_in[2];
    const float* b1l   = (const float*)d_in[3];
    const float* W1r   = (const float*)d_in[4];
    const float* b1r   = (const float*)d_in[5];
    const float* att1  = (const float*)d_in[6];
    const float* bias1 = (const float*)d_in[7];
    const float* l1W   = (const float*)d_in[8];
    const float* l1b   = (const float*)d_in[9];
    const float* W2l   = (const float*)d_in[10];
    const float* b2l   = (const float*)d_in[11];
    const float* W2r   = (const float*)d_in[12];
    const float* b2r   = (const float*)d_in[13];
    const float* att2  = (const float*)d_in[14];
    const float* bias2 = (const float*)d_in[15];
    const float* l2W   = (const float*)d_in[16];
    const float* l2b   = (const float*)d_in[17];
    float* out = (float*)d_out;

    detect_kernel<<<1, 32>>>(ei);
    convert_edges_kernel<<<(ET + 255) / 256, 256>>>(ei);
    zero_kernel<<<2048, 256>>>();

    gemm1_kernel<<<NN / 16, 64>>>(x, W1l, b1l, W1r, b1r, l1W, l1b);
    edge_logits1_kernel<<<(ET + 7) / 8, 256>>>(att1);
    edge_exp1_kernel<<<(ET + 255) / 256, 256>>>();
    edge_agg1_kernel<<<(ET + 7) / 8, 256>>>();
    node1_kernel<<<(NN * HH + 255) / 256, 256>>>(bias1);

    gemm2_kernel<<<NN / 16, 64>>>(W2l, b2l, W2r, b2r, l2W, l2b);
    edge_logits2_kernel<<<(ET + 7) / 8, 256>>>(att2);
    edge_exp2_kernel<<<(ET + 255) / 256, 256>>>();
    edge_agg2_kernel<<<(ET + 7) / 8, 256>>>();
    node2_kernel<<<(NN * 32 + 255) / 256, 256>>>(bias2, out);

    if (out_size >= NN * CC + 2 * EE)
        passthrough_kernel<<<(EE + 255) / 256, 256>>>(out);
}

// round 2
// speedup vs baseline: 1.9990x; 1.9990x over previous
#include <cuda_runtime.h>
#include <math.h>

#define NN 50000
#define EE 800000
#define ET (EE + NN)
#define FIN 256
#define HH 64
#define CC 40
#define NEG_SLOPE 0.2f

// ---------------- scratch (__device__ globals; no allocation) ----------------
static __device__ int g_is64;
static __device__ int g_src[ET];
static __device__ int g_dst[ET];
static __device__ int g_cnt[NN];
static __device__ int g_roff[NN + 1];
static __device__ int g_cursor[NN];
static __device__ int g_csrc[ET];

static __device__ float g_xl1[NN * HH];
static __device__ float g_xr1[NN * HH];
static __device__ float g_ln1[NN * HH];
static __device__ float g_h[NN * HH];

static __device__ float g_xl2[NN * CC];
static __device__ float g_xr2[NN * CC];
static __device__ float g_ln2[NN * CC];

// ---------------- edge index dtype detect ----------------
__global__ void detect_kernel(const void* edge) {
    const int* p = (const int*)edge;
    int ok64 = 1;
    for (int i = threadIdx.x * 2 + 1; i < 4096; i += 64)
        if (p[i] != 0) ok64 = 0;
    unsigned b = __ballot_sync(0xffffffffu, ok64);
    if (threadIdx.x == 0) g_is64 = (b == 0xffffffffu) ? 1 : 0;
}

__global__ void zero_cnt_kernel() {
    int i = blockIdx.x * blockDim.x + threadIdx.x;
    if (i < NN) g_cnt[i] = 0;
}

// convert edge list (+self loops) AND histogram dst
__global__ void convert_count_kernel(const void* edge) {
    int t = blockIdx.x * blockDim.x + threadIdx.x;
    if (t >= ET) return;
    int s, d;
    if (t >= EE) {
        s = t - EE; d = t - EE;
    } else if (g_is64) {
        const long long* p = (const long long*)edge;
        s = (int)p[t]; d = (int)p[EE + t];
    } else {
        const int* p = (const int*)edge;
        s = p[t]; d = p[EE + t];
    }
    g_src[t] = s;
    g_dst[t] = d;
    atomicAdd(&g_cnt[d], 1);
}

// single-block scan over 50k counts -> row offsets + cursor init
__global__ void __launch_bounds__(1024) scan_kernel() {
    __shared__ int warp_sums[32];
    int t = threadIdx.x;
    int lane = t & 31, w = t >> 5;
    int base = 0;
    if (t == 0) g_roff[0] = 0;
    for (int off = 0; off < NN; off += 1024) {
        int i = off + t;
        int v = (i < NN) ? g_cnt[i] : 0;
        int x = v;
#pragma unroll
        for (int dlt = 1; dlt < 32; dlt <<= 1) {
            int y = __shfl_up_sync(0xffffffffu, x, dlt);
            if (lane >= dlt) x += y;
        }
        if (lane == 31) warp_sums[w] = x;
        __syncthreads();
        if (w == 0) {
            int s = warp_sums[lane];
#pragma unroll
            for (int dlt = 1; dlt < 32; dlt <<= 1) {
                int y = __shfl_up_sync(0xffffffffu, s, dlt);
                if (lane >= dlt) s += y;
            }
            warp_sums[lane] = s;
        }
        __syncthreads();
        int prefix = (w > 0) ? warp_sums[w - 1] : 0;
        int excl = base + prefix + x - v;
        if (i < NN) {
            g_cursor[i] = excl;
            g_roff[i + 1] = excl + v;
        }
        base += warp_sums[31];
        __syncthreads();
    }
}

__global__ void scatter_kernel() {
    int t = blockIdx.x * blockDim.x + threadIdx.x;
    if (t >= ET) return;
    int d = g_dst[t];
    int pos = atomicAdd(&g_cursor[d], 1);
    g_csrc[pos] = g_src[t];
}

// ---------------- layer1 node GEMMs: xl1/xr1/lin1 fused, float4 ----------------
__global__ void __launch_bounds__(64) gemm1_kernel(
    const float* __restrict__ x,
    const float* __restrict__ Wl, const float* __restrict__ bl,
    const float* __restrict__ Wr, const float* __restrict__ br,
    const float* __restrict__ Wn, const float* __restrict__ bn) {
    __shared__ float4 xs[16 * 64];
    const int t = threadIdx.x;
    const int row0 = blockIdx.x * 16;
    const float4* x4 = (const float4*)(x + row0 * FIN);
#pragma unroll
    for (int i = 0; i < 16; i++) xs[i * 64 + t] = x4[i * 64 + t];
    __syncthreads();

    float al[16], ar[16], an[16];
#pragma unroll
    for (int m = 0; m < 16; m++) { al[m] = 0.f; ar[m] = 0.f; an[m] = 0.f; }

    for (int k4 = 0; k4 < 64; k4++) {
        int k = 4 * k4;
        float wl0 = __ldg(&Wl[(k + 0) * HH + t]);
        float wl1 = __ldg(&Wl[(k + 1) * HH + t]);
        float wl2 = __ldg(&Wl[(k + 2) * HH + t]);
        float wl3 = __ldg(&Wl[(k + 3) * HH + t]);
        float wr0 = __ldg(&Wr[(k + 0) * HH + t]);
        float wr1 = __ldg(&Wr[(k + 1) * HH + t]);
        float wr2 = __ldg(&Wr[(k + 2) * HH + t]);
        float wr3 = __ldg(&Wr[(k + 3) * HH + t]);
        float wn0 = __ldg(&Wn[(k + 0) * HH + t]);
        float wn1 = __ldg(&Wn[(k + 1) * HH + t]);
        float wn2 = __ldg(&Wn[(k + 2) * HH + t]);
        float wn3 = __ldg(&Wn[(k + 3) * HH + t]);
#pragma unroll
        for (int m = 0; m < 16; m++) {
            float4 xv = xs[m * 64 + k4];
            al[m] = fmaf(xv.x, wl0, al[m]);
            al[m] = fmaf(xv.y, wl1, al[m]);
            al[m] = fmaf(xv.z, wl2, al[m]);
            al[m] = fmaf(xv.w, wl3, al[m]);
            ar[m] = fmaf(xv.x, wr0, ar[m]);
            ar[m] = fmaf(xv.y, wr1, ar[m]);
            ar[m] = fmaf(xv.z, wr2, ar[m]);
            ar[m] = fmaf(xv.w, wr3, ar[m]);
            an[m] = fmaf(xv.x, wn0, an[m]);
            an[m] = fmaf(xv.y, wn1, an[m]);
            an[m] = fmaf(xv.z, wn2, an[m]);
            an[m] = fmaf(xv.w, wn3, an[m]);
        }
    }
    float vbl = __ldg(&bl[t]), vbr = __ldg(&br[t]), vbn = __ldg(&bn[t]);
#pragma unroll
    for (int m = 0; m < 16; m++) {
        int o = (row0 + m) * HH + t;
        g_xl1[o] = al[m] + vbl;
        g_xr1[o] = ar[m] + vbr;
        g_ln1[o] = an[m] + vbn;
    }
}

// ---------------- fused layer1 attention: online softmax, warp per dst ----------------
__global__ void attn1_kernel(const float* __restrict__ att,
                             const float* __restrict__ bias1) {
    int w = (blockIdx.x * blockDim.x + threadIdx.x) >> 5;
    int lane = threadIdx.x & 31;
    if (w >= NN) return;
    const float2* xl = (const float2*)g_xl1;
    float2 xr = ((const float2*)g_xr1)[w * 32 + lane];
    float2 at = ((const float2*)att)[lane];
    int beg = g_roff[w], end = g_roff[w + 1];

    float mx = -1e30f, den = 0.f, a0 = 0.f, a1 = 0.f;
    for (int e = beg; e < end; e++) {
        int s = g_csrc[e];
        float2 v = xl[s * 32 + lane];
        float m0 = v.x + xr.x;
        float m1 = v.y + xr.y;
        m0 = (m0 > 0.f) ? m0 : NEG_SLOPE * m0;
        m1 = (m1 > 0.f) ? m1 : NEG_SLOPE * m1;
        float p = m0 * at.x + m1 * at.y;
#pragma unroll
        for (int o = 16; o > 0; o >>= 1) p += __shfl_xor_sync(0xffffffffu, p, o);
        if (p > mx) {
            float sc = __expf(mx - p);
            den *= sc; a0 *= sc; a1 *= sc;
            mx = p;
        }
        float ww = __expf(p - mx);
        den += ww;
        a0 = fmaf(ww, v.x, a0);
        a1 = fmaf(ww, v.y, a1);
    }
    float inv = 1.f / den;
    float2 ln = ((const float2*)g_ln1)[w * 32 + lane];
    float b0 = __ldg(&bias1[2 * lane]);
    float b1 = __ldg(&bias1[2 * lane + 1]);
    float2 hv;
    hv.x = fmaxf(a0 * inv + b0 + ln.x, 0.f);
    hv.y = fmaxf(a1 * inv + b1 + ln.y, 0.f);
    ((float2*)g_h)[w * 32 + lane] = hv;
}

// ---------------- layer2 node GEMMs ----------------
__global__ void __launch_bounds__(64) gemm2_kernel(
    const float* __restrict__ Wl, const float* __restrict__ bl,
    const float* __restrict__ Wr, const float* __restrict__ br,
    const float* __restrict__ Wn, const float* __restrict__ bn) {
    __shared__ float4 hs[16 * 16];
    const int t = threadIdx.x;
    const int row0 = blockIdx.x * 16;
    const float4* h4 = (const float4*)(g_h + row0 * HH);
#pragma unroll
    for (int i = 0; i < 4; i++) hs[i * 64 + t] = h4[i * 64 + t];
    __syncthreads();

    const bool act = (t < CC);
    float al[16], ar[16], an[16];
#pragma unroll
    for (int m = 0; m < 16; m++) { al[m] = 0.f; ar[m] = 0.f; an[m] = 0.f; }

    for (int k4 = 0; k4 < 16; k4++) {
        int k = 4 * k4;
        float wl0 = act ? __ldg(&Wl[(k + 0) * CC + t]) : 0.f;
        float wl1 = act ? __ldg(&Wl[(k + 1) * CC + t]) : 0.f;
        float wl2 = act ? __ldg(&Wl[(k + 2) * CC + t]) : 0.f;
        float wl3 = act ? __ldg(&Wl[(k + 3) * CC + t]) : 0.f;
        float wr0 = act ? __ldg(&Wr[(k + 0) * CC + t]) : 0.f;
        float wr1 = act ? __ldg(&Wr[(k + 1) * CC + t]) : 0.f;
        float wr2 = act ? __ldg(&Wr[(k + 2) * CC + t]) : 0.f;
        float wr3 = act ? __ldg(&Wr[(k + 3) * CC + t]) : 0.f;
        float wn0 = act ? __ldg(&Wn[(k + 0) * CC + t]) : 0.f;
        float wn1 = act ? __ldg(&Wn[(k + 1) * CC + t]) : 0.f;
        float wn2 = act ? __ldg(&Wn[(k + 2) * CC + t]) : 0.f;
        float wn3 = act ? __ldg(&Wn[(k + 3) * CC + t]) : 0.f;
#pragma unroll
        for (int m = 0; m < 16; m++) {
            float4 xv = hs[m * 16 + k4];
            al[m] = fmaf(xv.x, wl0, al[m]);
            al[m] = fmaf(xv.y, wl1, al[m]);
            al[m] = fmaf(xv.z, wl2, al[m]);
            al[m] = fmaf(xv.w, wl3, al[m]);
            ar[m] = fmaf(xv.x, wr0, ar[m]);
            ar[m] = fmaf(xv.y, wr1, ar[m]);
            ar[m] = fmaf(xv.z, wr2, ar[m]);
            ar[m] = fmaf(xv.w, wr3, ar[m]);
            an[m] = fmaf(xv.x, wn0, an[m]);
            an[m] = fmaf(xv.y, wn1, an[m]);
            an[m] = fmaf(xv.z, wn2, an[m]);
            an[m] = fmaf(xv.w, wn3, an[m]);
        }
    }
    if (act) {
        float vbl = __ldg(&bl[t]), vbr = __ldg(&br[t]), vbn = __ldg(&bn[t]);
#pragma unroll
        for (int m = 0; m < 16; m++) {
            int o = (row0 + m) * CC + t;
            g_xl2[o] = al[m] + vbl;
            g_xr2[o] = ar[m] + vbr;
            g_ln2[o] = an[m] + vbn;
        }
    }
}

// ---------------- fused layer2 attention + log_softmax + output ----------------
__global__ void attn2_kernel(const float* __restrict__ att,
                             const float* __restrict__ bias2,
                             float* __restrict__ out) {
    int w = (blockIdx.x * blockDim.x + threadIdx.x) >> 5;
    int lane = threadIdx.x & 31;
    if (w >= NN) return;
    const bool act = (lane < CC / 2);  // 20 lanes hold 2 dims each
    const float2* xl = (const float2*)g_xl2;
    float2 xr = make_float2(0.f, 0.f), at = make_float2(0.f, 0.f);
    if (act) {
        xr = ((const float2*)g_xr2)[w * (CC / 2) + lane];
        at = ((const float2*)att)[lane];
    }
    int beg = g_roff[w], end = g_roff[w + 1];

    float mx = -1e30f, den = 0.f, a0 = 0.f, a1 = 0.f;
    for (int e = beg; e < end; e++) {
        int s = g_csrc[e];
        float2 v = make_float2(0.f, 0.f);
        if (act) v = xl[s * (CC / 2) + lane];
        float m0 = v.x + xr.x;
        float m1 = v.y + xr.y;
        m0 = (m0 > 0.f) ? m0 : NEG_SLOPE * m0;
        m1 = (m1 > 0.f) ? m1 : NEG_SLOPE * m1;
        float p = act ? (m0 * at.x + m1 * at.y) : 0.f;
#pragma unroll
        for (int o = 16; o > 0; o >>= 1) p += __shfl_xor_sync(0xffffffffu, p, o);
        if (p > mx) {
            float sc = __expf(mx - p);
            den *= sc; a0 *= sc; a1 *= sc;
            mx = p;
        }
        float ww = __expf(p - mx);
        den += ww;
        a0 = fmaf(ww, v.x, a0);
        a1 = fmaf(ww, v.y, a1);
    }
    float inv = 1.f / den;
    float o0 = -1e30f, o1 = -1e30f;
    if (act) {
        float2 ln = ((const float2*)g_ln2)[w * (CC / 2) + lane];
        o0 = a0 * inv + __ldg(&bias2[2 * lane]) + ln.x;
        o1 = a1 * inv + __ldg(&bias2[2 * lane + 1]) + ln.y;
    }
    // log_softmax over the 40 values
    float m2 = fmaxf(o0, o1);
#pragma unroll
    for (int o = 16; o > 0; o >>= 1) m2 = fmaxf(m2, __shfl_xor_sync(0xffffffffu, m2, o));
    float se = act ? (expf(o0 - m2) + expf(o1 - m2)) : 0.f;
#pragma unroll
    for (int o = 16; o > 0; o >>= 1) se += __shfl_xor_sync(0xffffffffu, se, o);
    float ls = logf(se);
    if (act) {
        out[w * CC + 2 * lane] = o0 - m2 - ls;
        out[w * CC + 2 * lane + 1] = o1 - m2 - ls;
    }
}

// edge_index passthrough (reference returns it as 2nd output), as float
__global__ void passthrough_kernel(float* __restrict__ out) {
    int t = blockIdx.x * blockDim.x + threadIdx.x;
    if (t >= EE) return;
    out[NN * CC + t] = (float)g_src[t];
    out[NN * CC + EE + t] = (float)g_dst[t];
}

// ---------------- launch ----------------
extern "C" void kernel_launch(void* const* d_in, const int* in_sizes, int n_in,
                              void* d_out, int out_size) {
    const float* x     = (const float*)d_in[0];
    const void*  ei    = d_in[1];
    const float* W1l   = (const float*)d_in[2];
    const float* b1l   = (const float*)d_in[3];
    const float* W1r   = (const float*)d_in[4];
    const float* b1r   = (const float*)d_in[5];
    const float* att1  = (const float*)d_in[6];
    const float* bias1 = (const float*)d_in[7];
    const float* l1W   = (const float*)d_in[8];
    const float* l1b   = (const float*)d_in[9];
    const float* W2l   = (const float*)d_in[10];
    const float* b2l   = (const float*)d_in[11];
    const float* W2r   = (const float*)d_in[12];
    const float* b2r   = (const float*)d_in[13];
    const float* att2  = (const float*)d_in[14];
    const float* bias2 = (const float*)d_in[15];
    const float* l2W   = (const float*)d_in[16];
    const float* l2b   = (const float*)d_in[17];
    float* out = (float*)d_out;

    detect_kernel<<<1, 32>>>(ei);
    zero_cnt_kernel<<<(NN + 255) / 256, 256>>>();
    convert_count_kernel<<<(ET + 255) / 256, 256>>>(ei);
    scan_kernel<<<1, 1024>>>();
    scatter_kernel<<<(ET + 255) / 256, 256>>>();

    gemm1_kernel<<<NN / 16, 64>>>(x, W1l, b1l, W1r, b1r, l1W, l1b);
    attn1_kernel<<<(NN * 32 + 255) / 256, 256>>>(att1, bias1);

    gemm2_kernel<<<NN / 16, 64>>>(W2l, b2l, W2r, b2r, l2W, l2b);
    attn2_kernel<<<(NN * 32 + 255) / 256, 256>>>(att2, bias2, out);

    if (out_size >= NN * CC + 2 * EE)
        passthrough_kernel<<<(EE + 255) / 256, 256>>>(out);
}

// round 3
// speedup vs baseline: 2.0706x; 1.0358x over previous
#include <cuda_runtime.h>
#include <math.h>

#define NN 50000
#define EE 800000
#define ET (EE + NN)
#define FIN 256
#define HH 64
#define CC 40
#define NEG_SLOPE 0.2f
#define NB ((NN + 255) / 256)

typedef unsigned long long u64;

// ---------------- scratch (__device__ globals; no allocation) ----------------
static __device__ int g_is64;
static __device__ int g_src[ET];
static __device__ int g_dst[ET];
static __device__ int g_cnt[NN];
static __device__ int g_roff[NN + 1];
static __device__ int g_cursor[NN];
static __device__ int g_csrc[ET];
static __device__ int g_bsum[NB];
static __device__ int g_bpre[NB];

static __device__ float g_xl1[NN * HH];
static __device__ float g_xr1[NN * HH];
static __device__ float g_ln1[NN * HH];
static __device__ float g_h[NN * HH];

static __device__ float g_xl2[NN * CC];
static __device__ float g_xr2[NN * CC];
static __device__ float g_ln2[NN * CC];

// ---------------- f32x2 packed-FMA helpers (sm_103a) ----------------
__device__ __forceinline__ void fma2(u64& acc, u64 a, u64 b) {
    asm("fma.rn.f32x2 %0, %1, %2, %0;" : "+l"(acc) : "l"(a), "l"(b));
}
__device__ __forceinline__ u64 pk(float lo, float hi) {
    u64 r;
    asm("mov.b64 %0, {%1, %2};" : "=l"(r) : "f"(lo), "f"(hi));
    return r;
}
__device__ __forceinline__ float plo(u64 v) { return __uint_as_float((unsigned)v); }
__device__ __forceinline__ float phi(u64 v) { return __uint_as_float((unsigned)(v >> 32)); }

// ---------------- edge index dtype detect ----------------
__global__ void detect_kernel(const void* edge) {
    const int* p = (const int*)edge;
    int ok64 = 1;
    for (int i = threadIdx.x * 2 + 1; i < 4096; i += 64)
        if (p[i] != 0) ok64 = 0;
    unsigned b = __ballot_sync(0xffffffffu, ok64);
    if (threadIdx.x == 0) g_is64 = (b == 0xffffffffu) ? 1 : 0;
}

__global__ void zero_cnt_kernel() {
    int i = blockIdx.x * blockDim.x + threadIdx.x;
    if (i < NN) g_cnt[i] = 0;
}

// convert edge list (+self loops), histogram dst, and emit edge_index passthrough
__global__ void convert_count_kernel(const void* edge, float* __restrict__ out, int do_pass) {
    int t = blockIdx.x * blockDim.x + threadIdx.x;
    if (t >= ET) return;
    int s, d;
    if (t >= EE) {
        s = t - EE; d = t - EE;
    } else if (g_is64) {
        const long long* p = (const long long*)edge;
        s = (int)p[t]; d = (int)p[EE + t];
    } else {
        const int* p = (const int*)edge;
        s = p[t]; d = p[EE + t];
    }
    g_src[t] = s;
    g_dst[t] = d;
    atomicAdd(&g_cnt[d], 1);
    if (do_pass && t < EE) {
        out[NN * CC + t] = (float)s;
        out[NN * CC + EE + t] = (float)d;
    }
}

// ---------------- 3-stage parallel scan over g_cnt ----------------
__global__ void bsum_kernel() {
    __shared__ int ws[8];
    int i = blockIdx.x * 256 + threadIdx.x;
    int lane = threadIdx.x & 31, w = threadIdx.x >> 5;
    int v = (i < NN) ? g_cnt[i] : 0;
#pragma unroll
    for (int o = 16; o > 0; o >>= 1) v += __shfl_xor_sync(0xffffffffu, v, o);
    if (lane == 0) ws[w] = v;
    __syncthreads();
    if (threadIdx.x == 0) {
        int s = 0;
#pragma unroll
        for (int k = 0; k < 8; k++) s += ws[k];
        g_bsum[blockIdx.x] = s;
    }
}

__global__ void bscan_kernel() {  // 1 block, 256 threads; NB <= 256
    __shared__ int ws[8];
    int t = threadIdx.x;
    int lane = t & 31, w = t >> 5;
    int v = (t < NB) ? g_bsum[t] : 0;
    int x = v;
#pragma unroll
    for (int dlt = 1; dlt < 32; dlt <<= 1) {
        int y = __shfl_up_sync(0xffffffffu, x, dlt);
        if (lane >= dlt) x += y;
    }
    if (lane == 31) ws[w] = x;
    __syncthreads();
    if (w == 0 && lane < 8) {
        int s = ws[lane];
#pragma unroll
        for (int dlt = 1; dlt < 8; dlt <<= 1) {
            int y = __shfl_up_sync(0xffu, s, dlt);
            if (lane >= dlt) s += y;
        }
        ws[lane] = s;
    }
    __syncthreads();
    int prefix = (w > 0) ? ws[w - 1] : 0;
    if (t < NB) g_bpre[t] = prefix + x - v;  // exclusive
}

__global__ void offs_kernel() {
    __shared__ int ws[8];
    int i = blockIdx.x * 256 + threadIdx.x;
    int lane = threadIdx.x & 31, w = threadIdx.x >> 5;
    int v = (i < NN) ? g_cnt[i] : 0;
    int x = v;
#pragma unroll
    for (int dlt = 1; dlt < 32; dlt <<= 1) {
        int y = __shfl_up_sync(0xffffffffu, x, dlt);
        if (lane >= dlt) x += y;
    }
    if (lane == 31) ws[w] = x;
    __syncthreads();
    if (w == 0 && lane < 8) {
        int s = ws[lane];
#pragma unroll
        for (int dlt = 1; dlt < 8; dlt <<= 1) {
            int y = __shfl_up_sync(0xffu, s, dlt);
            if (lane >= dlt) s += y;
        }
        ws[lane] = s;
    }
    __syncthreads();
    int prefix = (w > 0) ? ws[w - 1] : 0;
    int excl = g_bpre[blockIdx.x] + prefix + x - v;
    if (i < NN) {
        g_cursor[i] = excl;
        g_roff[i + 1] = excl + v;
    }
    if (i == 0) g_roff[0] = 0;
}

__global__ void scatter_kernel() {
    int t = blockIdx.x * blockDim.x + threadIdx.x;
    if (t >= ET) return;
    int d = g_dst[t];
    int pos = atomicAdd(&g_cursor[d], 1);
    g_csrc[pos] = g_src[t];
}

// ---------------- layer1 node GEMMs: xl1/xr1/lin1 fused, f32x2 ----------------
// 128 threads = 2 groups of 64 (one per output col); each group does 16 rows.
__global__ void __launch_bounds__(128) gemm1_kernel(
    const float* __restrict__ x,
    const float* __restrict__ Wl, const float* __restrict__ bl,
    const float* __restrict__ Wr, const float* __restrict__ br,
    const float* __restrict__ Wn, const float* __restrict__ bn) {
    __shared__ float4 xs[2][16 * 64];
    const int t = threadIdx.x & 63;
    const int g = threadIdx.x >> 6;
    const int row0 = blockIdx.x * 32 + g * 16;
    const float4* x4 = (const float4*)x;
#pragma unroll
    for (int i = 0; i < 16; i++) {
        int r = row0 + i;
        float4 v = make_float4(0.f, 0.f, 0.f, 0.f);
        if (r < NN) v = x4[r * 64 + t];
        xs[g][i * 64 + t] = v;
    }
    __syncthreads();

    u64 Pl[8], Pr[8], Pn[8];
#pragma unroll
    for (int m = 0; m < 8; m++) { Pl[m] = 0ull; Pr[m] = 0ull; Pn[m] = 0ull; }

    for (int k4 = 0; k4 < 64; k4++) {
        int k = 4 * k4;
        u64 WL[4], WR[4], WN[4];
#pragma unroll
        for (int j = 0; j < 4; j++) {
            float wl = __ldg(&Wl[(k + j) * HH + t]);
            float wr = __ldg(&Wr[(k + j) * HH + t]);
            float wn = __ldg(&Wn[(k + j) * HH + t]);
            WL[j] = pk(wl, wl);
            WR[j] = pk(wr, wr);
            WN[j] = pk(wn, wn);
        }
#pragma unroll
        for (int m2 = 0; m2 < 8; m2++) {
            float4 xa = xs[g][(2 * m2) * 64 + k4];
            float4 xb = xs[g][(2 * m2 + 1) * 64 + k4];
            u64 p0 = pk(xa.x, xb.x);
            u64 p1 = pk(xa.y, xb.y);
            u64 p2 = pk(xa.z, xb.z);
            u64 p3 = pk(xa.w, xb.w);
            fma2(Pl[m2], p0, WL[0]); fma2(Pr[m2], p0, WR[0]); fma2(Pn[m2], p0, WN[0]);
            fma2(Pl[m2], p1, WL[1]); fma2(Pr[m2], p1, WR[1]); fma2(Pn[m2], p1, WN[1]);
            fma2(Pl[m2], p2, WL[2]); fma2(Pr[m2], p2, WR[2]); fma2(Pn[m2], p2, WN[2]);
            fma2(Pl[m2], p3, WL[3]); fma2(Pr[m2], p3, WR[3]); fma2(Pn[m2], p3, WN[3]);
        }
    }
    float vbl = __ldg(&bl[t]), vbr = __ldg(&br[t]), vbn = __ldg(&bn[t]);
#pragma unroll
    for (int m2 = 0; m2 < 8; m2++) {
        int ra = row0 + 2 * m2, rb = ra + 1;
        if (ra < NN) {
            g_xl1[ra * HH + t] = plo(Pl[m2]) + vbl;
            g_xr1[ra * HH + t] = plo(Pr[m2]) + vbr;
            g_ln1[ra * HH + t] = plo(Pn[m2]) + vbn;
        }
        if (rb < NN) {
            g_xl1[rb * HH + t] = phi(Pl[m2]) + vbl;
            g_xr1[rb * HH + t] = phi(Pr[m2]) + vbr;
            g_ln1[rb * HH + t] = phi(Pn[m2]) + vbn;
        }
    }
}

// ---------------- fused layer1 attention: online softmax, warp per dst ----------------
__global__ void attn1_kernel(const float* __restrict__ att,
                             const float* __restrict__ bias1) {
    int w = (blockIdx.x * blockDim.x + threadIdx.x) >> 5;
    int lane = threadIdx.x & 31;
    if (w >= NN) return;
    const float2* xl = (const float2*)g_xl1;
    float2 xr = ((const float2*)g_xr1)[w * 32 + lane];
    float2 at = ((const float2*)att)[lane];
    int beg = g_roff[w], end = g_roff[w + 1];

    float mx = -1e30f, den = 0.f, a0 = 0.f, a1 = 0.f;
    int e = beg;
    for (; e + 1 < end; e += 2) {
        int s0 = g_csrc[e], s1 = g_csrc[e + 1];
        float2 v0 = xl[s0 * 32 + lane];
        float2 v1 = xl[s1 * 32 + lane];
        float q0 = v0.x + xr.x, q1 = v0.y + xr.y;
        float r0 = v1.x + xr.x, r1 = v1.y + xr.y;
        q0 = (q0 > 0.f) ? q0 : NEG_SLOPE * q0;
        q1 = (q1 > 0.f) ? q1 : NEG_SLOPE * q1;
        r0 = (r0 > 0.f) ? r0 : NEG_SLOPE * r0;
        r1 = (r1 > 0.f) ? r1 : NEG_SLOPE * r1;
        float pA = q0 * at.x + q1 * at.y;
        float pB = r0 * at.x + r1 * at.y;
#pragma unroll
        for (int o = 16; o > 0; o >>= 1) {
            pA += __shfl_xor_sync(0xffffffffu, pA, o);
            pB += __shfl_xor_sync(0xffffffffu, pB, o);
        }
        float nmx = fmaxf(mx, fmaxf(pA, pB));
        float sc = __expf(mx - nmx);
        float wA = __expf(pA - nmx);
        float wB = __expf(pB - nmx);
        den = den * sc + wA + wB;
        a0 = fmaf(a0, sc, fmaf(wA, v0.x, wB * v1.x));
        a1 = fmaf(a1, sc, fmaf(wA, v0.y, wB * v1.y));
        mx = nmx;
    }
    if (e < end) {
        int s = g_csrc[e];
        float2 v = xl[s * 32 + lane];
        float m0 = v.x + xr.x, m1 = v.y + xr.y;
        m0 = (m0 > 0.f) ? m0 : NEG_SLOPE * m0;
        m1 = (m1 > 0.f) ? m1 : NEG_SLOPE * m1;
        float p = m0 * at.x + m1 * at.y;
#pragma unroll
        for (int o = 16; o > 0; o >>= 1) p += __shfl_xor_sync(0xffffffffu, p, o);
        float nmx = fmaxf(mx, p);
        float sc = __expf(mx - nmx);
        float ww = __expf(p - nmx);
        den = den * sc + ww;
        a0 = fmaf(a0, sc, ww * v.x);
        a1 = fmaf(a1, sc, ww * v.y);
    }
    float inv = 1.f / den;
    float2 ln = ((const float2*)g_ln1)[w * 32 + lane];
    float b0 = __ldg(&bias1[2 * lane]);
    float b1 = __ldg(&bias1[2 * lane + 1]);
    float2 hv;
    hv.x = fmaxf(a0 * inv + b0 + ln.x, 0.f);
    hv.y = fmaxf(a1 * inv + b1 + ln.y, 0.f);
    ((float2*)g_h)[w * 32 + lane] = hv;
}

// ---------------- layer2 node GEMMs ----------------
__global__ void __launch_bounds__(64) gemm2_kernel(
    const float* __restrict__ Wl, const float* __restrict__ bl,
    const float* __restrict__ Wr, const float* __restrict__ br,
    const float* __restrict__ Wn, const float* __restrict__ bn) {
    __shared__ float4 hs[16 * 16];
    const int t = threadIdx.x;
    const int row0 = blockIdx.x * 16;
    const float4* h4 = (const float4*)(g_h + row0 * HH);
#pragma unroll
    for (int i = 0; i < 4; i++) hs[i * 64 + t] = h4[i * 64 + t];
    __syncthreads();

    const bool act = (t < CC);
    float al[16], ar[16], an[16];
#pragma unroll
    for (int m = 0; m < 16; m++) { al[m] = 0.f; ar[m] = 0.f; an[m] = 0.f; }

    for (int k4 = 0; k4 < 16; k4++) {
        int k = 4 * k4;
        float wl0 = act ? __ldg(&Wl[(k + 0) * CC + t]) : 0.f;
        float wl1 = act ? __ldg(&Wl[(k + 1) * CC + t]) : 0.f;
        float wl2 = act ? __ldg(&Wl[(k + 2) * CC + t]) : 0.f;
        float wl3 = act ? __ldg(&Wl[(k + 3) * CC + t]) : 0.f;
        float wr0 = act ? __ldg(&Wr[(k + 0) * CC + t]) : 0.f;
        float wr1 = act ? __ldg(&Wr[(k + 1) * CC + t]) : 0.f;
        float wr2 = act ? __ldg(&Wr[(k + 2) * CC + t]) : 0.f;
        float wr3 = act ? __ldg(&Wr[(k + 3) * CC + t]) : 0.f;
        float wn0 = act ? __ldg(&Wn[(k + 0) * CC + t]) : 0.f;
        float wn1 = act ? __ldg(&Wn[(k + 1) * CC + t]) : 0.f;
        float wn2 = act ? __ldg(&Wn[(k + 2) * CC + t]) : 0.f;
        float wn3 = act ? __ldg(&Wn[(k + 3) * CC + t]) : 0.f;
#pragma unroll
        for (int m = 0; m < 16; m++) {
            float4 xv = hs[m * 16 + k4];
            al[m] = fmaf(xv.x, wl0, al[m]);
            al[m] = fmaf(xv.y, wl1, al[m]);
            al[m] = fmaf(xv.z, wl2, al[m]);
            al[m] = fmaf(xv.w, wl3, al[m]);
            ar[m] = fmaf(xv.x, wr0, ar[m]);
            ar[m] = fmaf(xv.y, wr1, ar[m]);
            ar[m] = fmaf(xv.z, wr2, ar[m]);
            ar[m] = fmaf(xv.w, wr3, ar[m]);
            an[m] = fmaf(xv.x, wn0, an[m]);
            an[m] = fmaf(xv.y, wn1, an[m]);
            an[m] = fmaf(xv.z, wn2, an[m]);
            an[m] = fmaf(xv.w, wn3, an[m]);
        }
    }
    if (act) {
        float vbl = __ldg(&bl[t]), vbr = __ldg(&br[t]), vbn = __ldg(&bn[t]);
#pragma unroll
        for (int m = 0; m < 16; m++) {
            int o = (row0 + m) * CC + t;
            g_xl2[o] = al[m] + vbl;
            g_xr2[o] = ar[m] + vbr;
            g_ln2[o] = an[m] + vbn;
        }
    }
}

// ---------------- fused layer2 attention + log_softmax + output ----------------
__global__ void attn2_kernel(const float* __restrict__ att,
                             const float* __restrict__ bias2,
                             float* __restrict__ out) {
    int w = (blockIdx.x * blockDim.x + threadIdx.x) >> 5;
    int lane = threadIdx.x & 31;
    if (w >= NN) return;
    const bool act = (lane < CC / 2);
    const float2* xl = (const float2*)g_xl2;
    float2 xr = make_float2(0.f, 0.f), at = make_float2(0.f, 0.f);
    if (act) {
        xr = ((const float2*)g_xr2)[w * (CC / 2) + lane];
        at = ((const float2*)att)[lane];
    }
    int beg = g_roff[w], end = g_roff[w + 1];

    float mx = -1e30f, den = 0.f, a0 = 0.f, a1 = 0.f;
    int e = beg;
    for (; e + 1 < end; e += 2) {
        int s0 = g_csrc[e], s1 = g_csrc[e + 1];
        float2 v0 = make_float2(0.f, 0.f), v1 = make_float2(0.f, 0.f);
        if (act) {
            v0 = xl[s0 * (CC / 2) + lane];
            v1 = xl[s1 * (CC / 2) + lane];
        }
        float q0 = v0.x + xr.x, q1 = v0.y + xr.y;
        float r0 = v1.x + xr.x, r1 = v1.y + xr.y;
        q0 = (q0 > 0.f) ? q0 : NEG_SLOPE * q0;
        q1 = (q1 > 0.f) ? q1 : NEG_SLOPE * q1;
        r0 = (r0 > 0.f) ? r0 : NEG_SLOPE * r0;
        r1 = (r1 > 0.f) ? r1 : NEG_SLOPE * r1;
        float pA = q0 * at.x + q1 * at.y;
        float pB = r0 * at.x + r1 * at.y;
#pragma unroll
        for (int o = 16; o > 0; o >>= 1) {
            pA += __shfl_xor_sync(0xffffffffu, pA, o);
            pB += __shfl_xor_sync(0xffffffffu, pB, o);
        }
        float nmx = fmaxf(mx, fmaxf(pA, pB));
        float sc = __expf(mx - nmx);
        float wA = __expf(pA - nmx);
        float wB = __expf(pB - nmx);
        den = den * sc + wA + wB;
        a0 = fmaf(a0, sc, fmaf(wA, v0.x, wB * v1.x));
        a1 = fmaf(a1, sc, fmaf(wA, v0.y, wB * v1.y));
        mx = nmx;
    }
    if (e < end) {
        int s = g_csrc[e];
        float2 v = make_float2(0.f, 0.f);
        if (act) v = xl[s * (CC / 2) + lane];
        float m0 = v.x + xr.x, m1 = v.y + xr.y;
        m0 = (m0 > 0.f) ? m0 : NEG_SLOPE * m0;
        m1 = (m1 > 0.f) ? m1 : NEG_SLOPE * m1;
        float p = act ? (m0 * at.x + m1 * at.y) : 0.f;
#pragma unroll
        for (int o = 16; o > 0; o >>= 1) p += __shfl_xor_sync(0xffffffffu, p, o);
        float nmx = fmaxf(mx, p);
        float sc = __expf(mx - nmx);
        float ww = __expf(p - nmx);
        den = den * sc + ww;
        a0 = fmaf(a0, sc, ww * v.x);
        a1 = fmaf(a1, sc, ww * v.y);
    }
    float inv = 1.f / den;
    float o0 = -1e30f, o1 = -1e30f;
    if (act) {
        float2 ln = ((const float2*)g_ln2)[w * (CC / 2) + lane];
        o0 = a0 * inv + __ldg(&bias2[2 * lane]) + ln.x;
        o1 = a1 * inv + __ldg(&bias2[2 * lane + 1]) + ln.y;
    }
    float m2 = fmaxf(o0, o1);
#pragma unroll
    for (int o = 16; o > 0; o >>= 1) m2 = fmaxf(m2, __shfl_xor_sync(0xffffffffu, m2, o));
    float se = act ? (expf(o0 - m2) + expf(o1 - m2)) : 0.f;
#pragma unroll
    for (int o = 16; o > 0; o >>= 1) se += __shfl_xor_sync(0xffffffffu, se, o);
    float ls = logf(se);
    if (act) {
        out[w * CC + 2 * lane] = o0 - m2 - ls;
        out[w * CC + 2 * lane + 1] = o1 - m2 - ls;
    }
}

// ---------------- launch ----------------
extern "C" void kernel_launch(void* const* d_in, const int* in_sizes, int n_in,
                              void* d_out, int out_size) {
    const float* x     = (const float*)d_in[0];
    const void*  ei    = d_in[1];
    const float* W1l   = (const float*)d_in[2];
    const float* b1l   = (const float*)d_in[3];
    const float* W1r   = (const float*)d_in[4];
    const float* b1r   = (const float*)d_in[5];
    const float* att1  = (const float*)d_in[6];
    const float* bias1 = (const float*)d_in[7];
    const float* l1W   = (const float*)d_in[8];
    const float* l1b   = (const float*)d_in[9];
    const float* W2l   = (const float*)d_in[10];
    const float* b2l   = (const float*)d_in[11];
    const float* W2r   = (const float*)d_in[12];
    const float* b2r   = (const float*)d_in[13];
    const float* att2  = (const float*)d_in[14];
    const float* bias2 = (const float*)d_in[15];
    const float* l2W   = (const float*)d_in[16];
    const float* l2b   = (const float*)d_in[17];
    float* out = (float*)d_out;
    int do_pass = (out_size >= NN * CC + 2 * EE) ? 1 : 0;

    detect_kernel<<<1, 32>>>(ei);
    zero_cnt_kernel<<<NB, 256>>>();
    convert_count_kernel<<<(ET + 255) / 256, 256>>>(ei, out, do_pass);
    bsum_kernel<<<NB, 256>>>();
    bscan_kernel<<<1, 256>>>();
    offs_kernel<<<NB, 256>>>();
    scatter_kernel<<<(ET + 255) / 256, 256>>>();

    gemm1_kernel<<<(NN + 31) / 32, 128>>>(x, W1l, b1l, W1r, b1r, l1W, l1b);
    attn1_kernel<<<(NN * 32 + 255) / 256, 256>>>(att1, bias1);

    gemm2_kernel<<<NN / 16, 64>>>(W2l, b2l, W2r, b2r, l2W, l2b);
    attn2_kernel<<<(NN * 32 + 255) / 256, 256>>>(att2, bias2, out);
}